// round 15
// baseline (speedup 1.0000x reference)
#include <cuda_runtime.h>

#define N_NODES   100000
#define N_EDGES   800000
#define NF        64
#define NH        16
#define NG        64
#define FULLMASK  0xFFFFFFFFu

// ---------------- scratch (static device globals; no allocation) ----------------
__device__ __align__(16) float g_y[N_NODES * NH];    // x @ W1_rel
__device__ __align__(16) float g_agg[N_NODES * NH];  // x @ W1_root + b1, += seg_sum(y[src]) by dst
__device__ float g_t[N_NODES];         // relu(agg) . u
__device__ __align__(16) float4 g_u4[NH / 4];        // W2_rel @ Wlin  (packed)
__device__ __align__(16) float4 g_w4[NH / 4];        // W2_root @ Wlin (packed)
__device__ float g_c;                  // b2 . Wlin
__device__ float g_S[NG];
__device__ float g_E[NG];
__device__ float g_cnt[NG];

// ---------------- K0: fold layer-2 weights into vectors; zero accumulators ------
__global__ void k0_setup(const float* __restrict__ W2_rel,
                         const float* __restrict__ W2_root,
                         const float* __restrict__ b2,
                         const float* __restrict__ Wlin) {
    int t = threadIdx.x;
    __shared__ float su[NH], sw[NH];
    if (t < NH) {
        float u = 0.f, w = 0.f;
        #pragma unroll
        for (int j = 0; j < NH; ++j) {
            float lw = Wlin[j];
            u += W2_rel[t * NH + j]  * lw;
            w += W2_root[t * NH + j] * lw;
        }
        su[t] = u;
        sw[t] = w;
    }
    if (t == 32) {
        float c = 0.f;
        #pragma unroll
        for (int j = 0; j < NH; ++j) c += b2[j] * Wlin[j];
        g_c = c;
    }
    if (t < NG) { g_S[t] = 0.f; g_E[t] = 0.f; g_cnt[t] = 0.f; }
    __syncthreads();
    if (t < NH / 4) {
        g_u4[t] = make_float4(su[t*4], su[t*4+1], su[t*4+2], su[t*4+3]);
        g_w4[t] = make_float4(sw[t*4], sw[t*4+1], sw[t*4+2], sw[t*4+3]);
    }
}

// ---------------- K1: y = x @ W1_rel ; agg = x @ W1_root + b1 -------------------
__global__ void k1_node_proj(const float* __restrict__ x,
                             const float* __restrict__ W1_rel,
                             const float* __restrict__ W1_root,
                             const float* __restrict__ b1) {
    int i = blockIdx.x * blockDim.x + threadIdx.x;
    if (i >= N_NODES * NH) return;
    int n = i >> 4;
    int h = i & 15;
    const float4* xr = (const float4*)(x + (size_t)n * NF);
    float y = 0.f;
    float z = __ldg(b1 + h);
    #pragma unroll
    for (int f4 = 0; f4 < NF / 4; ++f4) {
        float4 xv = __ldg(xr + f4);
        int f = f4 * 4;
        y += xv.x * __ldg(W1_rel  + (f + 0) * NH + h);
        y += xv.y * __ldg(W1_rel  + (f + 1) * NH + h);
        y += xv.z * __ldg(W1_rel  + (f + 2) * NH + h);
        y += xv.w * __ldg(W1_rel  + (f + 3) * NH + h);
        z += xv.x * __ldg(W1_root + (f + 0) * NH + h);
        z += xv.y * __ldg(W1_root + (f + 1) * NH + h);
        z += xv.z * __ldg(W1_root + (f + 2) * NH + h);
        z += xv.w * __ldg(W1_root + (f + 3) * NH + h);
    }
    g_y[i]   = y;
    g_agg[i] = z;
}

// ---------------- K2: agg[dst] += y[src]  (1 thread/edge, MLP=4 both ways) ------
__global__ void k2_edge_scatter(const int* __restrict__ edge_index) {
    int e = blockIdx.x * blockDim.x + threadIdx.x;
    if (e >= N_EDGES) return;
    int src = __ldg(edge_index + e);
    int dst = __ldg(edge_index + N_EDGES + e);
    const float4* yr = (const float4*)(g_y + ((unsigned)src << 4));
    float4 v0 = __ldg(yr + 0);
    float4 v1 = __ldg(yr + 1);
    float4 v2 = __ldg(yr + 2);
    float4 v3 = __ldg(yr + 3);
    unsigned long long d =
        (unsigned long long)__cvta_generic_to_global(g_agg + ((unsigned)dst << 4));
    asm volatile("red.global.add.v4.f32 [%0], {%1, %2, %3, %4};"
                 :: "l"(d), "f"(v0.x), "f"(v0.y), "f"(v0.z), "f"(v0.w) : "memory");
    asm volatile("red.global.add.v4.f32 [%0], {%1, %2, %3, %4};"
                 :: "l"(d + 16), "f"(v1.x), "f"(v1.y), "f"(v1.z), "f"(v1.w) : "memory");
    asm volatile("red.global.add.v4.f32 [%0], {%1, %2, %3, %4};"
                 :: "l"(d + 32), "f"(v2.x), "f"(v2.y), "f"(v2.z), "f"(v2.w) : "memory");
    asm volatile("red.global.add.v4.f32 [%0], {%1, %2, %3, %4};"
                 :: "l"(d + 48), "f"(v3.x), "f"(v3.y), "f"(v3.z), "f"(v3.w) : "memory");
}

// ---------------- K3: h1 = relu(agg); per-node scalars; warp-binned pooling -----
// 1 thread per node, 4 independent float4 loads (MLP=4). batch sorted ->
// warp of 32 consecutive nodes is usually one graph: warp-reduce + 1 RED pair.
__global__ void k3_node_scalars(const int* __restrict__ batch) {
    int node = blockIdx.x * blockDim.x + threadIdx.x;
    bool valid = node < N_NODES;

    float4 a0, a1, a2, a3;
    int g = 0;
    if (valid) {
        const float4* ar = (const float4*)(g_agg + ((unsigned)node << 4));
        a0 = __ldg(ar + 0);
        a1 = __ldg(ar + 1);
        a2 = __ldg(ar + 2);
        a3 = __ldg(ar + 3);
        g = __ldg(batch + node);
    } else {
        a0 = a1 = a2 = a3 = make_float4(0.f, 0.f, 0.f, 0.f);
    }

    float4 w0 = g_w4[0], w1 = g_w4[1], w2 = g_w4[2], w3 = g_w4[3];
    float4 u0 = g_u4[0], u1 = g_u4[1], u2 = g_u4[2], u3 = g_u4[3];

    float s = 0.f, tv = 0.f;
    {
        float v;
        v = fmaxf(a0.x, 0.f); s += v * w0.x; tv += v * u0.x;
        v = fmaxf(a0.y, 0.f); s += v * w0.y; tv += v * u0.y;
        v = fmaxf(a0.z, 0.f); s += v * w0.z; tv += v * u0.z;
        v = fmaxf(a0.w, 0.f); s += v * w0.w; tv += v * u0.w;
        v = fmaxf(a1.x, 0.f); s += v * w1.x; tv += v * u1.x;
        v = fmaxf(a1.y, 0.f); s += v * w1.y; tv += v * u1.y;
        v = fmaxf(a1.z, 0.f); s += v * w1.z; tv += v * u1.z;
        v = fmaxf(a1.w, 0.f); s += v * w1.w; tv += v * u1.w;
        v = fmaxf(a2.x, 0.f); s += v * w2.x; tv += v * u2.x;
        v = fmaxf(a2.y, 0.f); s += v * w2.y; tv += v * u2.y;
        v = fmaxf(a2.z, 0.f); s += v * w2.z; tv += v * u2.z;
        v = fmaxf(a2.w, 0.f); s += v * w2.w; tv += v * u2.w;
        v = fmaxf(a3.x, 0.f); s += v * w3.x; tv += v * u3.x;
        v = fmaxf(a3.y, 0.f); s += v * w3.y; tv += v * u3.y;
        v = fmaxf(a3.z, 0.f); s += v * w3.z; tv += v * u3.z;
        v = fmaxf(a3.w, 0.f); s += v * w3.w; tv += v * u3.w;
    }
    if (valid) g_t[node] = tv;

    int lane = threadIdx.x & 31;
    unsigned ballot_valid = __ballot_sync(FULLMASK, valid);
    if (ballot_valid == 0) return;
    int nv = __popc(ballot_valid);

    int g0 = __shfl_sync(FULLMASK, g, 0);
    bool uniform = __all_sync(FULLMASK, (g == g0) || !valid);

    if (uniform) {
        float ss = valid ? s : 0.f;
        ss += __shfl_xor_sync(FULLMASK, ss, 1);
        ss += __shfl_xor_sync(FULLMASK, ss, 2);
        ss += __shfl_xor_sync(FULLMASK, ss, 4);
        ss += __shfl_xor_sync(FULLMASK, ss, 8);
        ss += __shfl_xor_sync(FULLMASK, ss, 16);
        if (lane == 0) {
            atomicAdd(&g_S[g0], ss + g_c * (float)nv);
            atomicAdd(&g_cnt[g0], (float)nv);
        }
    } else {
        if (valid) {
            atomicAdd(&g_S[g], s + g_c);
            atomicAdd(&g_cnt[g], 1.f);
        }
    }
}

// ---------------- K4: E[batch[dst]] += t[src]  (4 edges/thread, MLP=4) ----------
#define K4_EPT 4
__global__ void k4_edge_scalar(const int* __restrict__ edge_index,
                               const int* __restrict__ batch) {
    __shared__ float sE[NG];
    int t = threadIdx.x;
    if (t < NG) sE[t] = 0.f;
    __syncthreads();

    int base = blockIdx.x * blockDim.x * K4_EPT + t;
    int e0 = base;
    int e1 = base + blockDim.x;
    int e2 = base + blockDim.x * 2;
    int e3 = base + blockDim.x * 3;

    int s0 = 0, s1 = 0, s2 = 0, s3 = 0;
    int d0 = 0, d1 = 0, d2 = 0, d3 = 0;
    bool b0 = e0 < N_EDGES, b1 = e1 < N_EDGES, b2 = e2 < N_EDGES, b3 = e3 < N_EDGES;
    if (b0) { s0 = __ldg(edge_index + e0); d0 = __ldg(edge_index + N_EDGES + e0); }
    if (b1) { s1 = __ldg(edge_index + e1); d1 = __ldg(edge_index + N_EDGES + e1); }
    if (b2) { s2 = __ldg(edge_index + e2); d2 = __ldg(edge_index + N_EDGES + e2); }
    if (b3) { s3 = __ldg(edge_index + e3); d3 = __ldg(edge_index + N_EDGES + e3); }

    float t0 = 0.f, t1 = 0.f, t2 = 0.f, t3 = 0.f;
    int   gg0 = 0, gg1 = 0, gg2 = 0, gg3 = 0;
    if (b0) { t0 = __ldg(g_t + s0); gg0 = __ldg(batch + d0); }
    if (b1) { t1 = __ldg(g_t + s1); gg1 = __ldg(batch + d1); }
    if (b2) { t2 = __ldg(g_t + s2); gg2 = __ldg(batch + d2); }
    if (b3) { t3 = __ldg(g_t + s3); gg3 = __ldg(batch + d3); }

    if (b0) atomicAdd(&sE[gg0], t0);
    if (b1) atomicAdd(&sE[gg1], t1);
    if (b2) atomicAdd(&sE[gg2], t2);
    if (b3) atomicAdd(&sE[gg3], t3);

    __syncthreads();
    if (t < NG && sE[t] != 0.f) atomicAdd(&g_E[t], sE[t]);
}

// ---------------- K5: out[g] = (S+E)/max(cnt,1) + blin ---------------------------
__global__ void k5_final(const float* __restrict__ blin, float* __restrict__ out) {
    int g = threadIdx.x;
    if (g < NG) {
        float cnt = g_cnt[g];
        out[g] = (g_S[g] + g_E[g]) / fmaxf(cnt, 1.f) + blin[0];
    }
}

extern "C" void kernel_launch(void* const* d_in, const int* in_sizes, int n_in,
                              void* d_out, int out_size) {
    const float* x       = (const float*)d_in[0];
    const int*   eidx    = (const int*)d_in[1];    // int32 (JAX x64 disabled)
    const int*   batch   = (const int*)d_in[2];    // int32
    const float* W1_rel  = (const float*)d_in[3];
    const float* W1_root = (const float*)d_in[4];
    const float* b1      = (const float*)d_in[5];
    const float* W2_rel  = (const float*)d_in[6];
    const float* W2_root = (const float*)d_in[7];
    const float* b2      = (const float*)d_in[8];
    const float* Wlin    = (const float*)d_in[9];
    const float* blin    = (const float*)d_in[10];
    float* out = (float*)d_out;

    k0_setup<<<1, 128>>>(W2_rel, W2_root, b2, Wlin);

    {
        int total = N_NODES * NH;
        int tpb = 256;
        k1_node_proj<<<(total + tpb - 1) / tpb, tpb>>>(x, W1_rel, W1_root, b1);
    }
    {
        int tpb = 256;
        k2_edge_scatter<<<(N_EDGES + tpb - 1) / tpb, tpb>>>(eidx);
    }
    {
        int tpb = 128;
        k3_node_scalars<<<(N_NODES + tpb - 1) / tpb, tpb>>>(batch);
    }
    {
        int tpb = 256;
        int per_block = tpb * K4_EPT;
        k4_edge_scalar<<<(N_EDGES + per_block - 1) / per_block, tpb>>>(eidx, batch);
    }
    k5_final<<<1, 64>>>(blin, out);
}

// round 16
// speedup vs baseline: 1.0036x; 1.0036x over previous
#include <cuda_runtime.h>

#define N_NODES   100000
#define N_EDGES   800000
#define NF        64
#define NH        16
#define NG        64
#define FULLMASK  0xFFFFFFFFu

// ---------------- scratch (static device globals; no allocation) ----------------
__device__ __align__(16) float g_y[N_NODES * NH];    // x @ W1_rel
__device__ __align__(16) float g_agg[N_NODES * NH];  // x @ W1_root + b1, += seg_sum(y[src]) by dst
__device__ float g_t[N_NODES];         // relu(agg) . u
__device__ __align__(16) float4 g_u4[NH / 4];        // W2_rel @ Wlin  (packed)
__device__ __align__(16) float4 g_w4[NH / 4];        // W2_root @ Wlin (packed)
__device__ float g_c;                  // b2 . Wlin
__device__ float g_S[NG];
__device__ float g_E[NG];
__device__ float g_cnt[NG];

// ---------------- K0: fold layer-2 weights into vectors; zero accumulators ------
__global__ void k0_setup(const float* __restrict__ W2_rel,
                         const float* __restrict__ W2_root,
                         const float* __restrict__ b2,
                         const float* __restrict__ Wlin) {
    int t = threadIdx.x;
    __shared__ float su[NH], sw[NH];
    if (t < NH) {
        float u = 0.f, w = 0.f;
        #pragma unroll
        for (int j = 0; j < NH; ++j) {
            float lw = Wlin[j];
            u += W2_rel[t * NH + j]  * lw;
            w += W2_root[t * NH + j] * lw;
        }
        su[t] = u;
        sw[t] = w;
    }
    if (t == 32) {
        float c = 0.f;
        #pragma unroll
        for (int j = 0; j < NH; ++j) c += b2[j] * Wlin[j];
        g_c = c;
    }
    if (t < NG) { g_S[t] = 0.f; g_E[t] = 0.f; g_cnt[t] = 0.f; }
    __syncthreads();
    if (t < NH / 4) {
        g_u4[t] = make_float4(su[t*4], su[t*4+1], su[t*4+2], su[t*4+3]);
        g_w4[t] = make_float4(sw[t*4], sw[t*4+1], sw[t*4+2], sw[t*4+3]);
    }
}

// ---------------- K1: y = x @ W1_rel ; agg = x @ W1_root + b1 -------------------
__global__ void k1_node_proj(const float* __restrict__ x,
                             const float* __restrict__ W1_rel,
                             const float* __restrict__ W1_root,
                             const float* __restrict__ b1) {
    int i = blockIdx.x * blockDim.x + threadIdx.x;
    if (i >= N_NODES * NH) return;
    int n = i >> 4;
    int h = i & 15;
    const float4* xr = (const float4*)(x + (size_t)n * NF);
    float y = 0.f;
    float z = __ldg(b1 + h);
    #pragma unroll
    for (int f4 = 0; f4 < NF / 4; ++f4) {
        float4 xv = __ldg(xr + f4);
        int f = f4 * 4;
        y += xv.x * __ldg(W1_rel  + (f + 0) * NH + h);
        y += xv.y * __ldg(W1_rel  + (f + 1) * NH + h);
        y += xv.z * __ldg(W1_rel  + (f + 2) * NH + h);
        y += xv.w * __ldg(W1_rel  + (f + 3) * NH + h);
        z += xv.x * __ldg(W1_root + (f + 0) * NH + h);
        z += xv.y * __ldg(W1_root + (f + 1) * NH + h);
        z += xv.z * __ldg(W1_root + (f + 2) * NH + h);
        z += xv.w * __ldg(W1_root + (f + 3) * NH + h);
    }
    g_y[i]   = y;
    g_agg[i] = z;
}

// ---------------- K2: agg[dst] += y[src]  (1 thread/edge, MLP=4 both ways) ------
__global__ void k2_edge_scatter(const int* __restrict__ edge_index) {
    int e = blockIdx.x * blockDim.x + threadIdx.x;
    if (e >= N_EDGES) return;
    int src = __ldg(edge_index + e);
    int dst = __ldg(edge_index + N_EDGES + e);
    const float4* yr = (const float4*)(g_y + ((unsigned)src << 4));
    float4 v0 = __ldg(yr + 0);
    float4 v1 = __ldg(yr + 1);
    float4 v2 = __ldg(yr + 2);
    float4 v3 = __ldg(yr + 3);
    unsigned long long d =
        (unsigned long long)__cvta_generic_to_global(g_agg + ((unsigned)dst << 4));
    asm volatile("red.global.add.v4.f32 [%0], {%1, %2, %3, %4};"
                 :: "l"(d), "f"(v0.x), "f"(v0.y), "f"(v0.z), "f"(v0.w) : "memory");
    asm volatile("red.global.add.v4.f32 [%0], {%1, %2, %3, %4};"
                 :: "l"(d + 16), "f"(v1.x), "f"(v1.y), "f"(v1.z), "f"(v1.w) : "memory");
    asm volatile("red.global.add.v4.f32 [%0], {%1, %2, %3, %4};"
                 :: "l"(d + 32), "f"(v2.x), "f"(v2.y), "f"(v2.z), "f"(v2.w) : "memory");
    asm volatile("red.global.add.v4.f32 [%0], {%1, %2, %3, %4};"
                 :: "l"(d + 48), "f"(v3.x), "f"(v3.y), "f"(v3.z), "f"(v3.w) : "memory");
}

// ---------------- K3: h1 = relu(agg); per-node scalars; warp-binned pooling -----
// 1 thread per node, 4 independent float4 loads (MLP=4). batch sorted ->
// warp of 32 consecutive nodes is usually one graph: warp-reduce + 1 RED pair.
__global__ void k3_node_scalars(const int* __restrict__ batch) {
    int node = blockIdx.x * blockDim.x + threadIdx.x;
    bool valid = node < N_NODES;

    float4 a0, a1, a2, a3;
    int g = 0;
    if (valid) {
        const float4* ar = (const float4*)(g_agg + ((unsigned)node << 4));
        a0 = __ldg(ar + 0);
        a1 = __ldg(ar + 1);
        a2 = __ldg(ar + 2);
        a3 = __ldg(ar + 3);
        g = __ldg(batch + node);
    } else {
        a0 = a1 = a2 = a3 = make_float4(0.f, 0.f, 0.f, 0.f);
    }

    float4 w0 = g_w4[0], w1 = g_w4[1], w2 = g_w4[2], w3 = g_w4[3];
    float4 u0 = g_u4[0], u1 = g_u4[1], u2 = g_u4[2], u3 = g_u4[3];

    float s = 0.f, tv = 0.f;
    {
        float v;
        v = fmaxf(a0.x, 0.f); s += v * w0.x; tv += v * u0.x;
        v = fmaxf(a0.y, 0.f); s += v * w0.y; tv += v * u0.y;
        v = fmaxf(a0.z, 0.f); s += v * w0.z; tv += v * u0.z;
        v = fmaxf(a0.w, 0.f); s += v * w0.w; tv += v * u0.w;
        v = fmaxf(a1.x, 0.f); s += v * w1.x; tv += v * u1.x;
        v = fmaxf(a1.y, 0.f); s += v * w1.y; tv += v * u1.y;
        v = fmaxf(a1.z, 0.f); s += v * w1.z; tv += v * u1.z;
        v = fmaxf(a1.w, 0.f); s += v * w1.w; tv += v * u1.w;
        v = fmaxf(a2.x, 0.f); s += v * w2.x; tv += v * u2.x;
        v = fmaxf(a2.y, 0.f); s += v * w2.y; tv += v * u2.y;
        v = fmaxf(a2.z, 0.f); s += v * w2.z; tv += v * u2.z;
        v = fmaxf(a2.w, 0.f); s += v * w2.w; tv += v * u2.w;
        v = fmaxf(a3.x, 0.f); s += v * w3.x; tv += v * u3.x;
        v = fmaxf(a3.y, 0.f); s += v * w3.y; tv += v * u3.y;
        v = fmaxf(a3.z, 0.f); s += v * w3.z; tv += v * u3.z;
        v = fmaxf(a3.w, 0.f); s += v * w3.w; tv += v * u3.w;
    }
    if (valid) g_t[node] = tv;

    int lane = threadIdx.x & 31;
    unsigned ballot_valid = __ballot_sync(FULLMASK, valid);
    if (ballot_valid == 0) return;
    int nv = __popc(ballot_valid);

    int g0 = __shfl_sync(FULLMASK, g, 0);
    bool uniform = __all_sync(FULLMASK, (g == g0) || !valid);

    if (uniform) {
        float ss = valid ? s : 0.f;
        ss += __shfl_xor_sync(FULLMASK, ss, 1);
        ss += __shfl_xor_sync(FULLMASK, ss, 2);
        ss += __shfl_xor_sync(FULLMASK, ss, 4);
        ss += __shfl_xor_sync(FULLMASK, ss, 8);
        ss += __shfl_xor_sync(FULLMASK, ss, 16);
        if (lane == 0) {
            atomicAdd(&g_S[g0], ss + g_c * (float)nv);
            atomicAdd(&g_cnt[g0], (float)nv);
        }
    } else {
        if (valid) {
            atomicAdd(&g_S[g], s + g_c);
            atomicAdd(&g_cnt[g], 1.f);
        }
    }
}

// ---------------- K4: E[batch[dst]] += t[src]  (4 edges/thread, MLP=4) ----------
#define K4_EPT 4
__global__ void k4_edge_scalar(const int* __restrict__ edge_index,
                               const int* __restrict__ batch) {
    __shared__ float sE[NG];
    int t = threadIdx.x;
    if (t < NG) sE[t] = 0.f;
    __syncthreads();

    int base = blockIdx.x * blockDim.x * K4_EPT + t;
    int e0 = base;
    int e1 = base + blockDim.x;
    int e2 = base + blockDim.x * 2;
    int e3 = base + blockDim.x * 3;

    int s0 = 0, s1 = 0, s2 = 0, s3 = 0;
    int d0 = 0, d1 = 0, d2 = 0, d3 = 0;
    bool b0 = e0 < N_EDGES, b1 = e1 < N_EDGES, b2 = e2 < N_EDGES, b3 = e3 < N_EDGES;
    if (b0) { s0 = __ldg(edge_index + e0); d0 = __ldg(edge_index + N_EDGES + e0); }
    if (b1) { s1 = __ldg(edge_index + e1); d1 = __ldg(edge_index + N_EDGES + e1); }
    if (b2) { s2 = __ldg(edge_index + e2); d2 = __ldg(edge_index + N_EDGES + e2); }
    if (b3) { s3 = __ldg(edge_index + e3); d3 = __ldg(edge_index + N_EDGES + e3); }

    float t0 = 0.f, t1 = 0.f, t2 = 0.f, t3 = 0.f;
    int   gg0 = 0, gg1 = 0, gg2 = 0, gg3 = 0;
    if (b0) { t0 = __ldg(g_t + s0); gg0 = __ldg(batch + d0); }
    if (b1) { t1 = __ldg(g_t + s1); gg1 = __ldg(batch + d1); }
    if (b2) { t2 = __ldg(g_t + s2); gg2 = __ldg(batch + d2); }
    if (b3) { t3 = __ldg(g_t + s3); gg3 = __ldg(batch + d3); }

    if (b0) atomicAdd(&sE[gg0], t0);
    if (b1) atomicAdd(&sE[gg1], t1);
    if (b2) atomicAdd(&sE[gg2], t2);
    if (b3) atomicAdd(&sE[gg3], t3);

    __syncthreads();
    if (t < NG && sE[t] != 0.f) atomicAdd(&g_E[t], sE[t]);
}

// ---------------- K5: out[g] = (S+E)/max(cnt,1) + blin ---------------------------
__global__ void k5_final(const float* __restrict__ blin, float* __restrict__ out) {
    int g = threadIdx.x;
    if (g < NG) {
        float cnt = g_cnt[g];
        out[g] = (g_S[g] + g_E[g]) / fmaxf(cnt, 1.f) + blin[0];
    }
}

extern "C" void kernel_launch(void* const* d_in, const int* in_sizes, int n_in,
                              void* d_out, int out_size) {
    const float* x       = (const float*)d_in[0];
    const int*   eidx    = (const int*)d_in[1];    // int32 (JAX x64 disabled)
    const int*   batch   = (const int*)d_in[2];    // int32
    const float* W1_rel  = (const float*)d_in[3];
    const float* W1_root = (const float*)d_in[4];
    const float* b1      = (const float*)d_in[5];
    const float* W2_rel  = (const float*)d_in[6];
    const float* W2_root = (const float*)d_in[7];
    const float* b2      = (const float*)d_in[8];
    const float* Wlin    = (const float*)d_in[9];
    const float* blin    = (const float*)d_in[10];
    float* out = (float*)d_out;

    k0_setup<<<1, 128>>>(W2_rel, W2_root, b2, Wlin);

    {
        int total = N_NODES * NH;
        int tpb = 256;
        k1_node_proj<<<(total + tpb - 1) / tpb, tpb>>>(x, W1_rel, W1_root, b1);
    }
    {
        int tpb = 256;
        k2_edge_scatter<<<(N_EDGES + tpb - 1) / tpb, tpb>>>(eidx);
    }
    {
        int tpb = 128;
        k3_node_scalars<<<(N_NODES + tpb - 1) / tpb, tpb>>>(batch);
    }
    {
        int tpb = 256;
        int per_block = tpb * K4_EPT;
        k4_edge_scalar<<<(N_EDGES + per_block - 1) / per_block, tpb>>>(eidx, batch);
    }
    k5_final<<<1, 64>>>(blin, out);
}

// round 17
// speedup vs baseline: 1.2540x; 1.2495x over previous
#include <cuda_runtime.h>

#define N_NODES   100000
#define N_EDGES   800000
#define NF        64
#define NH        16
#define NG        64
#define FULLMASK  0xFFFFFFFFu

// ---------------- scratch (static device globals; no allocation) ----------------
__device__ __align__(16) float g_y[N_NODES * NH];    // x @ W1_rel
__device__ __align__(16) float g_agg[N_NODES * NH];  // x @ W1_root + b1, += seg_sum(y[src]) by dst
__device__ float g_t[N_NODES];         // relu(agg) . u
__device__ __align__(16) float4 g_u4[NH / 4];        // W2_rel @ Wlin  (packed)
__device__ __align__(16) float4 g_w4[NH / 4];        // W2_root @ Wlin (packed)
__device__ float g_c;                  // b2 . Wlin
__device__ float g_S[NG];
__device__ float g_E[NG];
__device__ float g_cnt[NG];
__device__ unsigned g_tick;            // k4 completion ticket

// ---------------- K1: y = x @ W1_rel ; agg = x @ W1_root + b1 -------------------
// Register-blocked: 1 thread = 1 node, 32 outputs in f32x2 accumulators,
// weights staged in smem (broadcast LDS.128), fma.rn.f32x2 main loop.
// Block 0 is a setup block (folds old k0 + ticket reset).
__global__ void __launch_bounds__(256)
k1_node_proj(const float* __restrict__ x,
             const float* __restrict__ W1_rel,
             const float* __restrict__ W1_root,
             const float* __restrict__ b1,
             const float* __restrict__ W2_rel,
             const float* __restrict__ W2_root,
             const float* __restrict__ b2,
             const float* __restrict__ Wlin) {
    if (blockIdx.x == 0) {
        int t = threadIdx.x;
        __shared__ float su[NH], sw[NH];
        if (t < NH) {
            float u = 0.f, w = 0.f;
            #pragma unroll
            for (int j = 0; j < NH; ++j) {
                float lw = Wlin[j];
                u += W2_rel[t * NH + j]  * lw;
                w += W2_root[t * NH + j] * lw;
            }
            su[t] = u;
            sw[t] = w;
        }
        if (t == 32) {
            float c = 0.f;
            #pragma unroll
            for (int j = 0; j < NH; ++j) c += b2[j] * Wlin[j];
            g_c = c;
        }
        if (t < NG) { g_S[t] = 0.f; g_E[t] = 0.f; g_cnt[t] = 0.f; }
        if (t == 64) g_tick = 0u;
        __syncthreads();
        if (t < NH / 4) {
            g_u4[t] = make_float4(su[t*4], su[t*4+1], su[t*4+2], su[t*4+3]);
            g_w4[t] = make_float4(sw[t*4], sw[t*4+1], sw[t*4+2], sw[t*4+3]);
        }
        return;
    }

    // sW[0] = W1_rel rows, sW[1] = W1_root rows; each row 16 floats = 64B.
    __shared__ __align__(16) float sW[2][NF][NH];
    __shared__ __align__(16) float sb[NH];
    int tid = threadIdx.x;
    #pragma unroll
    for (int k = 0; k < 4; ++k) {
        int i = tid + k * 256;            // 1024 floats per matrix
        sW[0][i >> 4][i & 15] = W1_rel[i];
        sW[1][i >> 4][i & 15] = W1_root[i];
    }
    if (tid < NH) sb[tid] = b1[tid];
    __syncthreads();

    int node = (blockIdx.x - 1) * blockDim.x + tid;
    if (node >= N_NODES) return;

    const float4* xr = (const float4*)(x + (size_t)node * NF);

    unsigned long long accy[8], accz[8];
    #pragma unroll
    for (int p = 0; p < 8; ++p) {
        accy[p] = 0ull;
        unsigned lo = __float_as_uint(sb[2 * p]);
        unsigned hi = __float_as_uint(sb[2 * p + 1]);
        asm("mov.b64 %0, {%1, %2};" : "=l"(accz[p]) : "r"(lo), "r"(hi));
    }

    #pragma unroll
    for (int f4 = 0; f4 < NF / 4; ++f4) {
        float4 xv = __ldg(xr + f4);
        #pragma unroll
        for (int s = 0; s < 4; ++s) {
            int f = f4 * 4 + s;
            float xs = (s == 0) ? xv.x : (s == 1) ? xv.y : (s == 2) ? xv.z : xv.w;
            unsigned long long xx;
            asm("mov.b64 %0, {%1, %1};" : "=l"(xx) : "r"(__float_as_uint(xs)));
            const ulonglong2* wr = (const ulonglong2*)sW[0][f];
            const ulonglong2* wo = (const ulonglong2*)sW[1][f];
            #pragma unroll
            for (int j = 0; j < 4; ++j) {
                ulonglong2 a = wr[j];
                ulonglong2 b = wo[j];
                asm("fma.rn.f32x2 %0, %1, %2, %0;" : "+l"(accy[2*j  ]) : "l"(a.x), "l"(xx));
                asm("fma.rn.f32x2 %0, %1, %2, %0;" : "+l"(accy[2*j+1]) : "l"(a.y), "l"(xx));
                asm("fma.rn.f32x2 %0, %1, %2, %0;" : "+l"(accz[2*j  ]) : "l"(b.x), "l"(xx));
                asm("fma.rn.f32x2 %0, %1, %2, %0;" : "+l"(accz[2*j+1]) : "l"(b.y), "l"(xx));
            }
        }
    }

    ulonglong2* yo = (ulonglong2*)(g_y   + ((unsigned)node << 4));
    ulonglong2* zo = (ulonglong2*)(g_agg + ((unsigned)node << 4));
    #pragma unroll
    for (int p = 0; p < 4; ++p) {
        yo[p] = make_ulonglong2(accy[2*p], accy[2*p+1]);
        zo[p] = make_ulonglong2(accz[2*p], accz[2*p+1]);
    }
}

// ---------------- K2: agg[dst] += y[src]  (1 thread/edge, MLP=4 both ways) ------
__global__ void k2_edge_scatter(const int* __restrict__ edge_index) {
    int e = blockIdx.x * blockDim.x + threadIdx.x;
    if (e >= N_EDGES) return;
    int src = __ldg(edge_index + e);
    int dst = __ldg(edge_index + N_EDGES + e);
    const float4* yr = (const float4*)(g_y + ((unsigned)src << 4));
    float4 v0 = __ldg(yr + 0);
    float4 v1 = __ldg(yr + 1);
    float4 v2 = __ldg(yr + 2);
    float4 v3 = __ldg(yr + 3);
    unsigned long long d =
        (unsigned long long)__cvta_generic_to_global(g_agg + ((unsigned)dst << 4));
    asm volatile("red.global.add.v4.f32 [%0], {%1, %2, %3, %4};"
                 :: "l"(d), "f"(v0.x), "f"(v0.y), "f"(v0.z), "f"(v0.w) : "memory");
    asm volatile("red.global.add.v4.f32 [%0], {%1, %2, %3, %4};"
                 :: "l"(d + 16), "f"(v1.x), "f"(v1.y), "f"(v1.z), "f"(v1.w) : "memory");
    asm volatile("red.global.add.v4.f32 [%0], {%1, %2, %3, %4};"
                 :: "l"(d + 32), "f"(v2.x), "f"(v2.y), "f"(v2.z), "f"(v2.w) : "memory");
    asm volatile("red.global.add.v4.f32 [%0], {%1, %2, %3, %4};"
                 :: "l"(d + 48), "f"(v3.x), "f"(v3.y), "f"(v3.z), "f"(v3.w) : "memory");
}

// ---------------- K3: h1 = relu(agg); per-node scalars; warp-binned pooling -----
__global__ void k3_node_scalars(const int* __restrict__ batch) {
    int node = blockIdx.x * blockDim.x + threadIdx.x;
    bool valid = node < N_NODES;

    float4 a0, a1, a2, a3;
    int g = 0;
    if (valid) {
        const float4* ar = (const float4*)(g_agg + ((unsigned)node << 4));
        a0 = __ldg(ar + 0);
        a1 = __ldg(ar + 1);
        a2 = __ldg(ar + 2);
        a3 = __ldg(ar + 3);
        g = __ldg(batch + node);
    } else {
        a0 = a1 = a2 = a3 = make_float4(0.f, 0.f, 0.f, 0.f);
    }

    float4 w0 = g_w4[0], w1 = g_w4[1], w2 = g_w4[2], w3 = g_w4[3];
    float4 u0 = g_u4[0], u1 = g_u4[1], u2 = g_u4[2], u3 = g_u4[3];

    float s = 0.f, tv = 0.f;
    {
        float v;
        v = fmaxf(a0.x, 0.f); s += v * w0.x; tv += v * u0.x;
        v = fmaxf(a0.y, 0.f); s += v * w0.y; tv += v * u0.y;
        v = fmaxf(a0.z, 0.f); s += v * w0.z; tv += v * u0.z;
        v = fmaxf(a0.w, 0.f); s += v * w0.w; tv += v * u0.w;
        v = fmaxf(a1.x, 0.f); s += v * w1.x; tv += v * u1.x;
        v = fmaxf(a1.y, 0.f); s += v * w1.y; tv += v * u1.y;
        v = fmaxf(a1.z, 0.f); s += v * w1.z; tv += v * u1.z;
        v = fmaxf(a1.w, 0.f); s += v * w1.w; tv += v * u1.w;
        v = fmaxf(a2.x, 0.f); s += v * w2.x; tv += v * u2.x;
        v = fmaxf(a2.y, 0.f); s += v * w2.y; tv += v * u2.y;
        v = fmaxf(a2.z, 0.f); s += v * w2.z; tv += v * u2.z;
        v = fmaxf(a2.w, 0.f); s += v * w2.w; tv += v * u2.w;
        v = fmaxf(a3.x, 0.f); s += v * w3.x; tv += v * u3.x;
        v = fmaxf(a3.y, 0.f); s += v * w3.y; tv += v * u3.y;
        v = fmaxf(a3.z, 0.f); s += v * w3.z; tv += v * u3.z;
        v = fmaxf(a3.w, 0.f); s += v * w3.w; tv += v * u3.w;
    }
    if (valid) g_t[node] = tv;

    int lane = threadIdx.x & 31;
    unsigned ballot_valid = __ballot_sync(FULLMASK, valid);
    if (ballot_valid == 0) return;
    int nv = __popc(ballot_valid);

    int g0 = __shfl_sync(FULLMASK, g, 0);
    bool uniform = __all_sync(FULLMASK, (g == g0) || !valid);

    if (uniform) {
        float ss = valid ? s : 0.f;
        ss += __shfl_xor_sync(FULLMASK, ss, 1);
        ss += __shfl_xor_sync(FULLMASK, ss, 2);
        ss += __shfl_xor_sync(FULLMASK, ss, 4);
        ss += __shfl_xor_sync(FULLMASK, ss, 8);
        ss += __shfl_xor_sync(FULLMASK, ss, 16);
        if (lane == 0) {
            atomicAdd(&g_S[g0], ss + g_c * (float)nv);
            atomicAdd(&g_cnt[g0], (float)nv);
        }
    } else {
        if (valid) {
            atomicAdd(&g_S[g], s + g_c);
            atomicAdd(&g_cnt[g], 1.f);
        }
    }
}

// ---------------- K4: E[batch[dst]] += t[src]; last block writes final out ------
#define K4_EPT 4
__global__ void k4_edge_scalar(const int* __restrict__ edge_index,
                               const int* __restrict__ batch,
                               const float* __restrict__ blin,
                               float* __restrict__ out) {
    __shared__ float sE[NG];
    __shared__ bool is_last;
    int t = threadIdx.x;
    if (t < NG) sE[t] = 0.f;
    __syncthreads();

    int base = blockIdx.x * blockDim.x * K4_EPT + t;
    int e0 = base;
    int e1 = base + blockDim.x;
    int e2 = base + blockDim.x * 2;
    int e3 = base + blockDim.x * 3;

    int s0 = 0, s1 = 0, s2 = 0, s3 = 0;
    int d0 = 0, d1 = 0, d2 = 0, d3 = 0;
    bool b0 = e0 < N_EDGES, b1 = e1 < N_EDGES, b2 = e2 < N_EDGES, b3 = e3 < N_EDGES;
    if (b0) { s0 = __ldg(edge_index + e0); d0 = __ldg(edge_index + N_EDGES + e0); }
    if (b1) { s1 = __ldg(edge_index + e1); d1 = __ldg(edge_index + N_EDGES + e1); }
    if (b2) { s2 = __ldg(edge_index + e2); d2 = __ldg(edge_index + N_EDGES + e2); }
    if (b3) { s3 = __ldg(edge_index + e3); d3 = __ldg(edge_index + N_EDGES + e3); }

    float t0 = 0.f, t1 = 0.f, t2 = 0.f, t3 = 0.f;
    int   gg0 = 0, gg1 = 0, gg2 = 0, gg3 = 0;
    if (b0) { t0 = __ldg(g_t + s0); gg0 = __ldg(batch + d0); }
    if (b1) { t1 = __ldg(g_t + s1); gg1 = __ldg(batch + d1); }
    if (b2) { t2 = __ldg(g_t + s2); gg2 = __ldg(batch + d2); }
    if (b3) { t3 = __ldg(g_t + s3); gg3 = __ldg(batch + d3); }

    if (b0) atomicAdd(&sE[gg0], t0);
    if (b1) atomicAdd(&sE[gg1], t1);
    if (b2) atomicAdd(&sE[gg2], t2);
    if (b3) atomicAdd(&sE[gg3], t3);

    __syncthreads();
    if (t < NG && sE[t] != 0.f) atomicAdd(&g_E[t], sE[t]);

    // completion ticket: last block computes the final output (fuses old k5)
    __threadfence();
    if (t == 0) {
        unsigned r = atomicAdd(&g_tick, 1u);
        is_last = (r == gridDim.x - 1);
    }
    __syncthreads();
    if (is_last && t < NG) {
        float cnt = g_cnt[t];
        out[t] = (g_S[t] + g_E[t]) / fmaxf(cnt, 1.f) + blin[0];
    }
}

extern "C" void kernel_launch(void* const* d_in, const int* in_sizes, int n_in,
                              void* d_out, int out_size) {
    const float* x       = (const float*)d_in[0];
    const int*   eidx    = (const int*)d_in[1];    // int32 (JAX x64 disabled)
    const int*   batch   = (const int*)d_in[2];    // int32
    const float* W1_rel  = (const float*)d_in[3];
    const float* W1_root = (const float*)d_in[4];
    const float* b1      = (const float*)d_in[5];
    const float* W2_rel  = (const float*)d_in[6];
    const float* W2_root = (const float*)d_in[7];
    const float* b2      = (const float*)d_in[8];
    const float* Wlin    = (const float*)d_in[9];
    const float* blin    = (const float*)d_in[10];
    float* out = (float*)d_out;

    {
        int tpb = 256;
        int node_blocks = (N_NODES + tpb - 1) / tpb;
        k1_node_proj<<<node_blocks + 1, tpb>>>(x, W1_rel, W1_root, b1,
                                               W2_rel, W2_root, b2, Wlin);
    }
    {
        int tpb = 256;
        k2_edge_scatter<<<(N_EDGES + tpb - 1) / tpb, tpb>>>(eidx);
    }
    {
        int tpb = 128;
        k3_node_scalars<<<(N_NODES + tpb - 1) / tpb, tpb>>>(batch);
    }
    {
        int tpb = 256;
        int per_block = tpb * K4_EPT;
        k4_edge_scalar<<<(N_EDGES + per_block - 1) / per_block, tpb>>>(eidx, batch, blin, out);
    }
}